// round 15
// baseline (speedup 1.0000x reference)
#include <cuda_runtime.h>
#include <cuda_fp16.h>
#include <math.h>
#include <stdint.h>

#define HH   2048
#define IMOE 1408
#define NE   8
#define TT   2048
#define ISH  2816

// ---------------- scratch (__device__ globals) ----------------
__device__ int   g_cnt[NE];
__device__ int   g_rows[NE * TT];
__device__ int   g_tok2row[TT * 2];
__device__ float g_wt[TT * 2];

__device__ __half g_x16[(size_t)TT * HH];
__device__ __half g_w2 [(size_t)NE * 2 * IMOE * HH];
__device__ __half g_dw [(size_t)NE * HH * IMOE];
__device__ __half g_sw2[(size_t)2 * ISH * HH];
__device__ __half g_sdw[(size_t)HH * ISH];
__device__ __half g_act[(size_t)NE * TT * IMOE];
__device__ __half g_acs[(size_t)TT * ISH];
__device__ float g_y [(size_t)NE * TT * HH];

// ---------------- helpers ----------------
__device__ __forceinline__ uint32_t smem_u32(const void* p) {
    uint32_t a;
    asm("{ .reg .u64 t; cvta.to.shared.u64 t, %1; cvt.u32.u64 %0, t; }"
        : "=r"(a) : "l"(p));
    return a;
}
__device__ __forceinline__ void ldsm4(uint32_t* r, uint32_t addr) {
    asm volatile("ldmatrix.sync.aligned.m8n8.x4.shared.b16 {%0,%1,%2,%3}, [%4];"
                 : "=r"(r[0]), "=r"(r[1]), "=r"(r[2]), "=r"(r[3]) : "r"(addr));
}
__device__ __forceinline__ void mma16816(float* d, const uint32_t* a,
                                         uint32_t b0, uint32_t b1) {
    asm volatile("mma.sync.aligned.m16n8k16.row.col.f32.f16.f16.f32 "
                 "{%0,%1,%2,%3}, {%4,%5,%6,%7}, {%8,%9}, {%0,%1,%2,%3};"
                 : "+f"(d[0]), "+f"(d[1]), "+f"(d[2]), "+f"(d[3])
                 : "r"(a[0]), "r"(a[1]), "r"(a[2]), "r"(a[3]), "r"(b0), "r"(b1));
}
__device__ __forceinline__ void cpa16(uint32_t dst, const void* src, uint32_t sz) {
    asm volatile("cp.async.cg.shared.global [%0], [%1], 16, %2;"
                 :: "r"(dst), "l"(src), "r"(sz) : "memory");
}
#define CP_COMMIT() asm volatile("cp.async.commit_group;" ::: "memory")
#define CP_WAIT(n)  asm volatile("cp.async.wait_group %0;" :: "n"(n) : "memory")

// ---------------- fused conversion kernel ----------------
#define XN    ((size_t)TT * HH / 4)
#define W2N   ((size_t)NE * 2 * IMOE * HH / 4)
#define DWN   ((size_t)NE * HH * IMOE / 4)
#define SW2N  ((size_t)2 * ISH * HH / 4)
#define SDWN  ((size_t)HH * ISH / 4)
#define CVT_TOTAL (XN + W2N + DWN + SW2N + SDWN)

__device__ __forceinline__ void cvt_store(__half2* dst, size_t li, float4 v) {
    dst[2 * li]     = __half2(__float2half_rn(v.x), __float2half_rn(v.y));
    dst[2 * li + 1] = __half2(__float2half_rn(v.z), __float2half_rn(v.w));
}

__global__ void cvt_all(const float4* __restrict__ x,
                        const float4* __restrict__ gw, const float4* __restrict__ uw,
                        const float4* __restrict__ dw,
                        const float4* __restrict__ sgw, const float4* __restrict__ suw,
                        const float4* __restrict__ sdw,
                        __half2* __restrict__ x16, __half2* __restrict__ w2,
                        __half2* __restrict__ dw16, __half2* __restrict__ sw2,
                        __half2* __restrict__ sdw16) {
    size_t i = (size_t)blockIdx.x * blockDim.x + threadIdx.x;
    if (i >= CVT_TOTAL) return;
    if (i < XN) {
        cvt_store(x16, i, x[i]);
        return;
    }
    i -= XN;
    if (i < W2N) {
        const int K4 = HH / 4;
        int    k4  = (int)(i % K4);
        size_t row = i / K4;
        int    n   = (int)(row % (2 * IMOE));
        int    e   = (int)(row / (2 * IMOE));
        const float4* s = (n & 1) ? uw : gw;
        cvt_store(w2, i, s[((size_t)e * IMOE + (n >> 1)) * K4 + k4]);
        return;
    }
    i -= W2N;
    if (i < DWN) {
        cvt_store(dw16, i, dw[i]);
        return;
    }
    i -= DWN;
    if (i < SW2N) {
        const int K4 = HH / 4;
        int    k4  = (int)(i % K4);
        size_t row = i / K4;
        int    n   = (int)(row % (2 * ISH));
        const float4* s = (n & 1) ? suw : sgw;
        cvt_store(sw2, i, s[(size_t)(n >> 1) * K4 + k4]);
        return;
    }
    i -= SW2N;
    cvt_store(sdw16, i, sdw[i]);
}

// ---------------- misc kernels ----------------
__global__ void zero_cnt_kernel() {
    if (threadIdx.x < NE) g_cnt[threadIdx.x] = 0;
}

__global__ void router_kernel(const float* __restrict__ x,
                              const float* __restrict__ rw,
                              const float* __restrict__ bias) {
    int t    = (blockIdx.x * blockDim.x + threadIdx.x) >> 5;
    int lane = threadIdx.x & 31;
    if (t >= TT) return;
    const float* xt = x + (size_t)t * HH;

    float logits[NE];
#pragma unroll
    for (int e = 0; e < NE; e++) {
        const float* w = rw + e * HH;
        float s = 0.f;
        for (int h = lane; h < HH; h += 32) s = fmaf(xt[h], w[h], s);
#pragma unroll
        for (int o = 16; o; o >>= 1) s += __shfl_xor_sync(0xffffffffu, s, o);
        logits[e] = s;
    }
    if (lane != 0) return;

    float scores[NE], sfc[NE];
#pragma unroll
    for (int e = 0; e < NE; e++) {
        scores[e] = 1.f / (1.f + expf(-logits[e]));
        sfc[e]    = scores[e] + bias[e];
    }
    float gs[4];
#pragma unroll
    for (int g = 0; g < 4; g++) gs[g] = sfc[2 * g] + sfc[2 * g + 1];
    int g0 = 0;
#pragma unroll
    for (int g = 1; g < 4; g++) if (gs[g] > gs[g0]) g0 = g;
    int g1 = -1;
#pragma unroll
    for (int g = 0; g < 4; g++) {
        if (g == g0) continue;
        if (g1 < 0 || gs[g] > gs[g1]) g1 = g;
    }
    int i0 = -1; float v0 = -1.f;
#pragma unroll
    for (int e = 0; e < NE; e++) {
        int g = e >> 1;
        float v = (g == g0 || g == g1) ? sfc[e] : 0.0f;
        if (v > v0) { v0 = v; i0 = e; }
    }
    int i1 = -1; float v1 = -1.f;
#pragma unroll
    for (int e = 0; e < NE; e++) {
        if (e == i0) continue;
        int g = e >> 1;
        float v = (g == g0 || g == g1) ? sfc[e] : 0.0f;
        if (v > v1) { v1 = v; i1 = e; }
    }
    float w0 = scores[i0], w1 = scores[i1];
    float inv = 2.5f / (w0 + w1 + 1e-20f);
    w0 *= inv; w1 *= inv;

    int p0 = atomicAdd(&g_cnt[i0], 1);
    g_rows[i0 * TT + p0] = t;
    g_tok2row[t * 2 + 0] = i0 * TT + p0;
    g_wt[t * 2 + 0]      = w0;
    int p1 = atomicAdd(&g_cnt[i1], 1);
    g_rows[i1 * TT + p1] = t;
    g_tok2row[t * 2 + 1] = i1 * TT + p1;
    g_wt[t * 2 + 1]      = w1;
}

// ---------------- fp16 HMMA GEMM: D[M,N] = A[M,K] @ B[N,K]^T ----------------
// 128x64 CTA tile, BK=32, 8 warps (4m x 2n), warp tile 32x32,
// 3-stage cp.async pipeline, single __syncthreads per chunk, 3 CTAs/SM.
// COMBINE variant (final shared-down GEMM): epilogue adds routed contributions.
#define ROWB   80
#define APLANE (128 * ROWB)       // 10240
#define BPLANE (64 * ROWB)        // 5120
#define STAGEB (APLANE + BPLANE)  // 15360
#define NSTG   3
#define SMEM_SZ (NSTG * STAGEB)   // 46080

template <int N, int K, bool ROUTED, bool GATHER, bool GATEUP, bool COMBINE>
__global__ __launch_bounds__(256, 3)
void hmma1(const __half* __restrict__ A, const __half* __restrict__ B,
           float* __restrict__ D, __half* __restrict__ P,
           const float* __restrict__ YR) {
    extern __shared__ __align__(128) char smem[];
    const int e  = blockIdx.z;
    const int M  = ROUTED ? g_cnt[e] : TT;
    const int m0 = blockIdx.y * 128;
    if (m0 >= M) return;
    const int n0   = blockIdx.x * 64;
    const int tid  = threadIdx.x;
    const int lane = tid & 31;
    const int wid  = tid >> 5;
    const int wm   = wid & 3;      // 4 m-slices of 32
    const int wn   = wid >> 2;     // 2 n-slices of 32
    const uint32_t sb0 = smem_u32(smem);

    // A loader: 2 threads per row (all 256 threads), 32B each
    const int lr = tid >> 1;
    const int hh = tid & 1;
    const __half* pA;
    uint32_t asz = 0;
    {
        int row = m0 + lr;
        size_t gr = 0;
        if (row < M) {
            gr  = GATHER ? (size_t)g_rows[e * TT + row]
                         : (ROUTED ? (size_t)e * TT + row : (size_t)row);
            asz = 16;
        }
        pA = A + gr * (size_t)K + hh * 16;
    }
    // B loader: threads <128, 2 threads per row (64 rows), 32B each
    const bool ldB = tid < 128;
    const __half* pB = B + (ROUTED ? (size_t)e * N * K : 0)
                         + (size_t)(n0 + (lr & 63)) * K + hh * 16;
    const uint32_t dstA = (uint32_t)lr * ROWB + (uint32_t)hh * 32;
    const uint32_t dstB = APLANE + (uint32_t)(lr & 63) * ROWB + (uint32_t)hh * 32;

    auto issue = [&](int c, int s) {
        uint32_t d = sb0 + (uint32_t)s * STAGEB;
        const __half* a0 = pA + c * 32;
        cpa16(d + dstA,      a0,     asz);
        cpa16(d + dstA + 16, a0 + 8, asz);
        if (ldB) {
            const __half* b0 = pB + c * 32;
            cpa16(d + dstB,      b0,     16);
            cpa16(d + dstB + 16, b0 + 8, 16);
        }
        CP_COMMIT();
    };

    float acc[2][4][4];
#pragma unroll
    for (int f = 0; f < 2; f++)
#pragma unroll
        for (int j = 0; j < 4; j++)
#pragma unroll
            for (int q = 0; q < 4; q++) acc[f][j][q] = 0.f;

    const int NCH = K / 32;
    issue(0, 0);
    issue(1, 1);

    for (int c = 0; c < NCH; c++) {
        const int s = c % NSTG;
        // stage c ready; collective sync also proves all warps done reading
        // stage (c-1) == (c+2)%NSTG, so it is safe to refill below.
        if (c + 1 < NCH) {
            CP_WAIT(1);
        } else {
            CP_WAIT(0);
        }
        __syncthreads();
        if (c + 2 < NCH) issue(c + 2, (c + 2) % NSTG);

        const uint32_t stg = sb0 + (uint32_t)s * STAGEB;
#pragma unroll
        for (int ks = 0; ks < 2; ks++) {
            const uint32_t cb = (uint32_t)(ks * 16 + (lane >> 4) * 8) * 2;
            uint32_t aF[2][4], bF[4][2];
#pragma unroll
            for (int f = 0; f < 2; f++) {
                uint32_t ra = (uint32_t)(wm * 32 + f * 16 + (lane & 15)) * ROWB + cb;
                ldsm4(aF[f], stg + ra);
            }
#pragma unroll
            for (int nb = 0; nb < 2; nb++) {
                uint32_t rb = APLANE + (uint32_t)(wn * 32 + nb * 16 + (lane & 15)) * ROWB + cb;
                uint32_t h4[4];
                ldsm4(h4, stg + rb);
                bF[2 * nb][0] = h4[0]; bF[2 * nb][1] = h4[2];
                bF[2 * nb + 1][0] = h4[1]; bF[2 * nb + 1][1] = h4[3];
            }
#pragma unroll
            for (int f = 0; f < 2; f++)
#pragma unroll
                for (int j = 0; j < 4; j++)
                    mma16816(acc[f][j], aF[f], bF[j][0], bF[j][1]);
        }
    }

    // ---- epilogue ----
    const size_t rowbase = ROUTED ? (size_t)e * TT : 0;
#pragma unroll
    for (int f = 0; f < 2; f++) {
#pragma unroll
        for (int half = 0; half < 2; half++) {
            int rloc = m0 + wm * 32 + f * 16 + (lane >> 2) + half * 8;
            if (rloc >= M) continue;
            size_t rg = rowbase + rloc;
            size_t r0 = 0, r1 = 0;
            float  cw0 = 0.f, cw1 = 0.f;
            if (COMBINE) {
                r0  = (size_t)g_tok2row[2 * rloc];
                r1  = (size_t)g_tok2row[2 * rloc + 1];
                cw0 = g_wt[2 * rloc];
                cw1 = g_wt[2 * rloc + 1];
            }
#pragma unroll
            for (int j = 0; j < 4; j++) {
                float vx = acc[f][j][half * 2 + 0];
                float vy = acc[f][j][half * 2 + 1];
                int cg = n0 + wn * 32 + j * 8 + (lane & 3) * 2;
                if (GATEUP) {
                    // vx = gate (even col), vy = up (odd col)
                    float a = vx / (1.f + expf(-vx)) * vy;
                    P[rg * (size_t)(N / 2) + (cg >> 1)] = __float2half_rn(a);
                } else if (COMBINE) {
                    float2 a = *(const float2*)(YR + r0 * (size_t)N + cg);
                    float2 b = *(const float2*)(YR + r1 * (size_t)N + cg);
                    float ox = fmaf(cw0, a.x, fmaf(cw1, b.x, vx));
                    float oy = fmaf(cw0, a.y, fmaf(cw1, b.y, vy));
                    *(float2*)(D + rg * (size_t)N + cg) = make_float2(ox, oy);
                } else {
                    *(float2*)(D + rg * (size_t)N + cg) = make_float2(vx, vy);
                }
            }
        }
    }
}

// ---------------- launch ----------------
extern "C" void kernel_launch(void* const* d_in, const int* in_sizes, int n_in,
                              void* d_out, int out_size) {
    const float* x    = (const float*)d_in[0];
    const float* rw   = (const float*)d_in[1];
    const float* bias = (const float*)d_in[2];
    const float* gw   = (const float*)d_in[3];
    const float* uw   = (const float*)d_in[4];
    const float* dw   = (const float*)d_in[5];
    const float* sgw  = (const float*)d_in[6];
    const float* suw  = (const float*)d_in[7];
    const float* sdw  = (const float*)d_in[8];
    float* out = (float*)d_out;

    __half *x16, *w2, *dwp, *sw2, *sdwp, *act, *acs;
    float *py;
    cudaGetSymbolAddress((void**)&x16,  g_x16);
    cudaGetSymbolAddress((void**)&w2,   g_w2);
    cudaGetSymbolAddress((void**)&dwp,  g_dw);
    cudaGetSymbolAddress((void**)&sw2,  g_sw2);
    cudaGetSymbolAddress((void**)&sdwp, g_sdw);
    cudaGetSymbolAddress((void**)&act,  g_act);
    cudaGetSymbolAddress((void**)&acs,  g_acs);
    cudaGetSymbolAddress((void**)&py,   g_y);

    cudaFuncSetAttribute(hmma1<2 * IMOE, HH, true,  true,  true,  false>, cudaFuncAttributeMaxDynamicSharedMemorySize, SMEM_SZ);
    cudaFuncSetAttribute(hmma1<HH, IMOE, true,  false, false, false>, cudaFuncAttributeMaxDynamicSharedMemorySize, SMEM_SZ);
    cudaFuncSetAttribute(hmma1<2 * ISH,  HH, false, false, true,  false>, cudaFuncAttributeMaxDynamicSharedMemorySize, SMEM_SZ);
    cudaFuncSetAttribute(hmma1<HH,  ISH, false, false, false, true >, cudaFuncAttributeMaxDynamicSharedMemorySize, SMEM_SZ);

    // node order (2 hidden harness launches precede these):
    zero_cnt_kernel<<<1, 32>>>();                                     // 0
    router_kernel<<<TT / 8, 256>>>(x, rw, bias);                      // 1
    {                                                                  // 2: all conversions
        size_t nblk = (CVT_TOTAL + 255) / 256;
        cvt_all<<<(unsigned)nblk, 256>>>(
            (const float4*)x, (const float4*)gw, (const float4*)uw, (const float4*)dw,
            (const float4*)sgw, (const float4*)suw, (const float4*)sdw,
            (__half2*)x16, (__half2*)w2, (__half2*)dwp, (__half2*)sw2, (__half2*)sdwp);
    }

    // 3: MAIN routed gate+up GEMM (ncu -s 5 lands here)
    hmma1<2 * IMOE, HH, true, true, true, false><<<dim3(2 * IMOE / 64, TT / 128, NE), 256, SMEM_SZ>>>(
        x16, w2, nullptr, act, nullptr);
    // 4: routed down GEMM -> g_y
    hmma1<HH, IMOE, true, false, false, false><<<dim3(HH / 64, TT / 128, NE), 256, SMEM_SZ>>>(
        act, dwp, py, nullptr, nullptr);
    // 5: shared gate+up GEMM
    hmma1<2 * ISH, HH, false, false, true, false><<<dim3(2 * ISH / 64, TT / 128, 1), 256, SMEM_SZ>>>(
        x16, sw2, nullptr, acs, nullptr);
    // 6: shared down GEMM with fused combine -> out
    hmma1<HH, ISH, false, false, false, true><<<dim3(HH / 64, TT / 128, 1), 256, SMEM_SZ>>>(
        acs, sdwp, out, nullptr, py);
}

// round 16
// speedup vs baseline: 1.5047x; 1.5047x over previous
#include <cuda_runtime.h>
#include <cuda_fp16.h>
#include <math.h>
#include <stdint.h>

#define HH   2048
#define IMOE 1408
#define NE   8
#define TT   2048
#define ISH  2816

// ---------------- scratch (__device__ globals) ----------------
__device__ int   g_cnt[NE];
__device__ int   g_rows[NE * TT];
__device__ int   g_tok2row[TT * 2];
__device__ float g_wt[TT * 2];

__device__ __half g_x16[(size_t)TT * HH];
__device__ __half g_w2 [(size_t)NE * 2 * IMOE * HH];
__device__ __half g_dw [(size_t)NE * HH * IMOE];
__device__ __half g_sw2[(size_t)2 * ISH * HH];
__device__ __half g_sdw[(size_t)HH * ISH];
__device__ __half g_act[(size_t)NE * TT * IMOE];
__device__ __half g_acs[(size_t)TT * ISH];
__device__ float g_y [(size_t)NE * TT * HH];

// ---------------- helpers ----------------
__device__ __forceinline__ uint32_t smem_u32(const void* p) {
    uint32_t a;
    asm("{ .reg .u64 t; cvta.to.shared.u64 t, %1; cvt.u32.u64 %0, t; }"
        : "=r"(a) : "l"(p));
    return a;
}
__device__ __forceinline__ void ldsm4(uint32_t* r, uint32_t addr) {
    asm volatile("ldmatrix.sync.aligned.m8n8.x4.shared.b16 {%0,%1,%2,%3}, [%4];"
                 : "=r"(r[0]), "=r"(r[1]), "=r"(r[2]), "=r"(r[3]) : "r"(addr));
}
__device__ __forceinline__ void mma16816(float* d, const uint32_t* a,
                                         uint32_t b0, uint32_t b1) {
    asm volatile("mma.sync.aligned.m16n8k16.row.col.f32.f16.f16.f32 "
                 "{%0,%1,%2,%3}, {%4,%5,%6,%7}, {%8,%9}, {%0,%1,%2,%3};"
                 : "+f"(d[0]), "+f"(d[1]), "+f"(d[2]), "+f"(d[3])
                 : "r"(a[0]), "r"(a[1]), "r"(a[2]), "r"(a[3]), "r"(b0), "r"(b1));
}
__device__ __forceinline__ void cpa16(uint32_t dst, const void* src, uint32_t sz) {
    asm volatile("cp.async.cg.shared.global [%0], [%1], 16, %2;"
                 :: "r"(dst), "l"(src), "r"(sz) : "memory");
}
#define CP_COMMIT() asm volatile("cp.async.commit_group;" ::: "memory")
#define CP_WAIT(n)  asm volatile("cp.async.wait_group %0;" :: "n"(n) : "memory")

// ---------------- fused conversion kernel ----------------
#define XN    ((size_t)TT * HH / 4)
#define W2N   ((size_t)NE * 2 * IMOE * HH / 4)
#define DWN   ((size_t)NE * HH * IMOE / 4)
#define SW2N  ((size_t)2 * ISH * HH / 4)
#define SDWN  ((size_t)HH * ISH / 4)
#define CVT_TOTAL (XN + W2N + DWN + SW2N + SDWN)

__device__ __forceinline__ void cvt_store(__half2* dst, size_t li, float4 v) {
    dst[2 * li]     = __half2(__float2half_rn(v.x), __float2half_rn(v.y));
    dst[2 * li + 1] = __half2(__float2half_rn(v.z), __float2half_rn(v.w));
}

__global__ void cvt_all(const float4* __restrict__ x,
                        const float4* __restrict__ gw, const float4* __restrict__ uw,
                        const float4* __restrict__ dw,
                        const float4* __restrict__ sgw, const float4* __restrict__ suw,
                        const float4* __restrict__ sdw,
                        __half2* __restrict__ x16, __half2* __restrict__ w2,
                        __half2* __restrict__ dw16, __half2* __restrict__ sw2,
                        __half2* __restrict__ sdw16) {
    size_t i = (size_t)blockIdx.x * blockDim.x + threadIdx.x;
    if (i >= CVT_TOTAL) return;
    if (i < XN) {
        cvt_store(x16, i, x[i]);
        return;
    }
    i -= XN;
    if (i < W2N) {
        const int K4 = HH / 4;
        int    k4  = (int)(i % K4);
        size_t row = i / K4;
        int    n   = (int)(row % (2 * IMOE));
        int    e   = (int)(row / (2 * IMOE));
        const float4* s = (n & 1) ? uw : gw;
        cvt_store(w2, i, s[((size_t)e * IMOE + (n >> 1)) * K4 + k4]);
        return;
    }
    i -= W2N;
    if (i < DWN) {
        cvt_store(dw16, i, dw[i]);
        return;
    }
    i -= DWN;
    if (i < SW2N) {
        const int K4 = HH / 4;
        int    k4  = (int)(i % K4);
        size_t row = i / K4;
        int    n   = (int)(row % (2 * ISH));
        const float4* s = (n & 1) ? suw : sgw;
        cvt_store(sw2, i, s[(size_t)(n >> 1) * K4 + k4]);
        return;
    }
    i -= SW2N;
    cvt_store(sdw16, i, sdw[i]);
}

// ---------------- misc kernels ----------------
__global__ void zero_cnt_kernel() {
    if (threadIdx.x < NE) g_cnt[threadIdx.x] = 0;
}

__global__ void router_kernel(const float* __restrict__ x,
                              const float* __restrict__ rw,
                              const float* __restrict__ bias) {
    int t    = (blockIdx.x * blockDim.x + threadIdx.x) >> 5;
    int lane = threadIdx.x & 31;
    if (t >= TT) return;
    const float* xt = x + (size_t)t * HH;

    float logits[NE];
#pragma unroll
    for (int e = 0; e < NE; e++) {
        const float* w = rw + e * HH;
        float s = 0.f;
        for (int h = lane; h < HH; h += 32) s = fmaf(xt[h], w[h], s);
#pragma unroll
        for (int o = 16; o; o >>= 1) s += __shfl_xor_sync(0xffffffffu, s, o);
        logits[e] = s;
    }
    if (lane != 0) return;

    float scores[NE], sfc[NE];
#pragma unroll
    for (int e = 0; e < NE; e++) {
        scores[e] = 1.f / (1.f + expf(-logits[e]));
        sfc[e]    = scores[e] + bias[e];
    }
    float gs[4];
#pragma unroll
    for (int g = 0; g < 4; g++) gs[g] = sfc[2 * g] + sfc[2 * g + 1];
    int g0 = 0;
#pragma unroll
    for (int g = 1; g < 4; g++) if (gs[g] > gs[g0]) g0 = g;
    int g1 = -1;
#pragma unroll
    for (int g = 0; g < 4; g++) {
        if (g == g0) continue;
        if (g1 < 0 || gs[g] > gs[g1]) g1 = g;
    }
    int i0 = -1; float v0 = -1.f;
#pragma unroll
    for (int e = 0; e < NE; e++) {
        int g = e >> 1;
        float v = (g == g0 || g == g1) ? sfc[e] : 0.0f;
        if (v > v0) { v0 = v; i0 = e; }
    }
    int i1 = -1; float v1 = -1.f;
#pragma unroll
    for (int e = 0; e < NE; e++) {
        if (e == i0) continue;
        int g = e >> 1;
        float v = (g == g0 || g == g1) ? sfc[e] : 0.0f;
        if (v > v1) { v1 = v; i1 = e; }
    }
    float w0 = scores[i0], w1 = scores[i1];
    float inv = 2.5f / (w0 + w1 + 1e-20f);
    w0 *= inv; w1 *= inv;

    int p0 = atomicAdd(&g_cnt[i0], 1);
    g_rows[i0 * TT + p0] = t;
    g_tok2row[t * 2 + 0] = i0 * TT + p0;
    g_wt[t * 2 + 0]      = w0;
    int p1 = atomicAdd(&g_cnt[i1], 1);
    g_rows[i1 * TT + p1] = t;
    g_tok2row[t * 2 + 1] = i1 * TT + p1;
    g_wt[t * 2 + 1]      = w1;
}

// ---------------- fp16 HMMA GEMM: D[M,N] = A[M,K] @ B[N,K]^T ----------------
// 128x64 CTA tile, BK=32, 8 warps (4m x 2n), warp tile 32x32,
// 3-stage cp.async pipeline, single __syncthreads per chunk, 3 CTAs/SM.
// COMBINE variant (final shared-down GEMM): epilogue adds routed contributions.
#define ROWB   80
#define APLANE (128 * ROWB)       // 10240
#define BPLANE (64 * ROWB)        // 5120
#define STAGEB (APLANE + BPLANE)  // 15360
#define NSTG   3
#define SMEM_SZ (NSTG * STAGEB)   // 46080

template <int N, int K, bool ROUTED, bool GATHER, bool GATEUP, bool COMBINE>
__global__ __launch_bounds__(256, 3)
void hmma1(const __half* __restrict__ A, const __half* __restrict__ B,
           float* __restrict__ D, __half* __restrict__ P,
           const float* __restrict__ YR) {
    extern __shared__ __align__(128) char smem[];
    const int e  = blockIdx.z;
    const int M  = ROUTED ? g_cnt[e] : TT;
    const int m0 = blockIdx.y * 128;
    if (m0 >= M) return;
    const int n0   = blockIdx.x * 64;
    const int tid  = threadIdx.x;
    const int lane = tid & 31;
    const int wid  = tid >> 5;
    const int wm   = wid & 3;      // 4 m-slices of 32
    const int wn   = wid >> 2;     // 2 n-slices of 32
    const uint32_t sb0 = smem_u32(smem);

    // A loader: 2 threads per row (all 256 threads), 32B each
    const int lr = tid >> 1;
    const int hh = tid & 1;
    const __half* pA;
    uint32_t asz = 0;
    {
        int row = m0 + lr;
        size_t gr = 0;
        if (row < M) {
            gr  = GATHER ? (size_t)g_rows[e * TT + row]
                         : (ROUTED ? (size_t)e * TT + row : (size_t)row);
            asz = 16;
        }
        pA = A + gr * (size_t)K + hh * 16;
    }
    // B loader: threads <128, 2 threads per row (64 rows), 32B each
    const bool ldB = tid < 128;
    const __half* pB = B + (ROUTED ? (size_t)e * N * K : 0)
                         + (size_t)(n0 + (lr & 63)) * K + hh * 16;
    const uint32_t dstA = (uint32_t)lr * ROWB + (uint32_t)hh * 32;
    const uint32_t dstB = APLANE + (uint32_t)(lr & 63) * ROWB + (uint32_t)hh * 32;

    auto issue = [&](int c, int s) {
        uint32_t d = sb0 + (uint32_t)s * STAGEB;
        const __half* a0 = pA + c * 32;
        cpa16(d + dstA,      a0,     asz);
        cpa16(d + dstA + 16, a0 + 8, asz);
        if (ldB) {
            const __half* b0 = pB + c * 32;
            cpa16(d + dstB,      b0,     16);
            cpa16(d + dstB + 16, b0 + 8, 16);
        }
        CP_COMMIT();
    };

    float acc[2][4][4];
#pragma unroll
    for (int f = 0; f < 2; f++)
#pragma unroll
        for (int j = 0; j < 4; j++)
#pragma unroll
            for (int q = 0; q < 4; q++) acc[f][j][q] = 0.f;

    // hoisted ldsm row offsets (stage-invariant)
    const uint32_t raBase0 = (uint32_t)(wm * 32 + (lane & 15)) * ROWB;
    const uint32_t raBase1 = (uint32_t)(wm * 32 + 16 + (lane & 15)) * ROWB;
    const uint32_t rbBase0 = APLANE + (uint32_t)(wn * 32 + (lane & 15)) * ROWB;
    const uint32_t rbBase1 = APLANE + (uint32_t)(wn * 32 + 16 + (lane & 15)) * ROWB;
    const uint32_t cbHalf  = (uint32_t)((lane >> 4) * 8) * 2;

    const int NCH = K / 32;
    issue(0, 0);
    issue(1, 1);

    int s = 0;          // stage of chunk c (manual wrap, no %)
    int sNext = 2;      // stage of chunk c+2
    for (int c = 0; c < NCH; c++) {
        if (c + 1 < NCH) {
            CP_WAIT(1);
        } else {
            CP_WAIT(0);
        }
        __syncthreads();
        if (c + 2 < NCH) issue(c + 2, sNext);

        const uint32_t stg = sb0 + (uint32_t)s * STAGEB;
#pragma unroll
        for (int ks = 0; ks < 2; ks++) {
            const uint32_t cb = cbHalf + (uint32_t)(ks * 32);
            uint32_t aF[2][4], bF[4][2];
            ldsm4(aF[0], stg + raBase0 + cb);
            ldsm4(aF[1], stg + raBase1 + cb);
            {
                uint32_t h4[4];
                ldsm4(h4, stg + rbBase0 + cb);
                bF[0][0] = h4[0]; bF[0][1] = h4[2];
                bF[1][0] = h4[1]; bF[1][1] = h4[3];
                ldsm4(h4, stg + rbBase1 + cb);
                bF[2][0] = h4[0]; bF[2][1] = h4[2];
                bF[3][0] = h4[1]; bF[3][1] = h4[3];
            }
#pragma unroll
            for (int f = 0; f < 2; f++)
#pragma unroll
                for (int j = 0; j < 4; j++)
                    mma16816(acc[f][j], aF[f], bF[j][0], bF[j][1]);
        }
        s     = (s     == NSTG - 1) ? 0 : s + 1;
        sNext = (sNext == NSTG - 1) ? 0 : sNext + 1;
    }

    // ---- epilogue ----
    const size_t rowbase = ROUTED ? (size_t)e * TT : 0;
#pragma unroll
    for (int f = 0; f < 2; f++) {
#pragma unroll
        for (int half = 0; half < 2; half++) {
            int rloc = m0 + wm * 32 + f * 16 + (lane >> 2) + half * 8;
            if (rloc >= M) continue;
            size_t rg = rowbase + rloc;
            size_t r0 = 0, r1 = 0;
            float  cw0 = 0.f, cw1 = 0.f;
            if (COMBINE) {
                r0  = (size_t)g_tok2row[2 * rloc];
                r1  = (size_t)g_tok2row[2 * rloc + 1];
                cw0 = g_wt[2 * rloc];
                cw1 = g_wt[2 * rloc + 1];
            }
#pragma unroll
            for (int j = 0; j < 4; j++) {
                float vx = acc[f][j][half * 2 + 0];
                float vy = acc[f][j][half * 2 + 1];
                int cg = n0 + wn * 32 + j * 8 + (lane & 3) * 2;
                if (GATEUP) {
                    // vx = gate (even col), vy = up (odd col)
                    float a = vx / (1.f + expf(-vx)) * vy;
                    P[rg * (size_t)(N / 2) + (cg >> 1)] = __float2half_rn(a);
                } else if (COMBINE) {
                    float2 a = *(const float2*)(YR + r0 * (size_t)N + cg);
                    float2 b = *(const float2*)(YR + r1 * (size_t)N + cg);
                    float ox = fmaf(cw0, a.x, fmaf(cw1, b.x, vx));
                    float oy = fmaf(cw0, a.y, fmaf(cw1, b.y, vy));
                    *(float2*)(D + rg * (size_t)N + cg) = make_float2(ox, oy);
                } else {
                    *(float2*)(D + rg * (size_t)N + cg) = make_float2(vx, vy);
                }
            }
        }
    }
}

// ---------------- launch ----------------
extern "C" void kernel_launch(void* const* d_in, const int* in_sizes, int n_in,
                              void* d_out, int out_size) {
    const float* x    = (const float*)d_in[0];
    const float* rw   = (const float*)d_in[1];
    const float* bias = (const float*)d_in[2];
    const float* gw   = (const float*)d_in[3];
    const float* uw   = (const float*)d_in[4];
    const float* dw   = (const float*)d_in[5];
    const float* sgw  = (const float*)d_in[6];
    const float* suw  = (const float*)d_in[7];
    const float* sdw  = (const float*)d_in[8];
    float* out = (float*)d_out;

    __half *x16, *w2, *dwp, *sw2, *sdwp, *act, *acs;
    float *py;
    cudaGetSymbolAddress((void**)&x16,  g_x16);
    cudaGetSymbolAddress((void**)&w2,   g_w2);
    cudaGetSymbolAddress((void**)&dwp,  g_dw);
    cudaGetSymbolAddress((void**)&sw2,  g_sw2);
    cudaGetSymbolAddress((void**)&sdwp, g_sdw);
    cudaGetSymbolAddress((void**)&act,  g_act);
    cudaGetSymbolAddress((void**)&acs,  g_acs);
    cudaGetSymbolAddress((void**)&py,   g_y);

    cudaFuncSetAttribute(hmma1<2 * IMOE, HH, true,  true,  true,  false>, cudaFuncAttributeMaxDynamicSharedMemorySize, SMEM_SZ);
    cudaFuncSetAttribute(hmma1<HH, IMOE, true,  false, false, false>, cudaFuncAttributeMaxDynamicSharedMemorySize, SMEM_SZ);
    cudaFuncSetAttribute(hmma1<2 * ISH,  HH, false, false, true,  false>, cudaFuncAttributeMaxDynamicSharedMemorySize, SMEM_SZ);
    cudaFuncSetAttribute(hmma1<HH,  ISH, false, false, false, true >, cudaFuncAttributeMaxDynamicSharedMemorySize, SMEM_SZ);

    // node order (2 hidden harness launches precede these):
    zero_cnt_kernel<<<1, 32>>>();                                     // 0
    router_kernel<<<TT / 8, 256>>>(x, rw, bias);                      // 1
    {                                                                  // 2: all conversions
        size_t nblk = (CVT_TOTAL + 255) / 256;
        cvt_all<<<(unsigned)nblk, 256>>>(
            (const float4*)x, (const float4*)gw, (const float4*)uw, (const float4*)dw,
            (const float4*)sgw, (const float4*)suw, (const float4*)sdw,
            (__half2*)x16, (__half2*)w2, (__half2*)dwp, (__half2*)sw2, (__half2*)sdwp);
    }

    // 3: MAIN routed gate+up GEMM (ncu -s 5 lands here)
    hmma1<2 * IMOE, HH, true, true, true, false><<<dim3(2 * IMOE / 64, TT / 128, NE), 256, SMEM_SZ>>>(
        x16, w2, nullptr, act, nullptr);
    // 4: routed down GEMM -> g_y
    hmma1<HH, IMOE, true, false, false, false><<<dim3(HH / 64, TT / 128, NE), 256, SMEM_SZ>>>(
        act, dwp, py, nullptr, nullptr);
    // 5: shared gate+up GEMM
    hmma1<2 * ISH, HH, false, false, true, false><<<dim3(2 * ISH / 64, TT / 128, 1), 256, SMEM_SZ>>>(
        x16, sw2, nullptr, acs, nullptr);
    // 6: shared down GEMM with fused combine -> out
    hmma1<HH, ISH, false, false, false, true><<<dim3(HH / 64, TT / 128, 1), 256, SMEM_SZ>>>(
        acs, sdwp, out, nullptr, py);
}

// round 17
// speedup vs baseline: 1.5455x; 1.0271x over previous
#include <cuda_runtime.h>
#include <cuda_fp16.h>
#include <math.h>
#include <stdint.h>

#define HH   2048
#define IMOE 1408
#define NE   8
#define TT   2048
#define ISH  2816

// ---------------- scratch (__device__ globals) ----------------
__device__ int   g_cnt[NE];
__device__ int   g_rows[NE * TT];
__device__ int   g_tok2row[TT * 2];
__device__ float g_wt[TT * 2];

__device__ __half g_x16[(size_t)TT * HH];
__device__ __half g_w2 [(size_t)NE * 2 * IMOE * HH];
__device__ __half g_dw [(size_t)NE * HH * IMOE];
__device__ __half g_sw2[(size_t)2 * ISH * HH];
__device__ __half g_sdw[(size_t)HH * ISH];
__device__ __half g_act[(size_t)NE * TT * IMOE];
__device__ __half g_acs[(size_t)TT * ISH];
__device__ float g_y [(size_t)NE * TT * HH];

// ---------------- helpers ----------------
__device__ __forceinline__ uint32_t smem_u32(const void* p) {
    uint32_t a;
    asm("{ .reg .u64 t; cvta.to.shared.u64 t, %1; cvt.u32.u64 %0, t; }"
        : "=r"(a) : "l"(p));
    return a;
}
__device__ __forceinline__ void ldsm4(uint32_t* r, uint32_t addr) {
    asm volatile("ldmatrix.sync.aligned.m8n8.x4.shared.b16 {%0,%1,%2,%3}, [%4];"
                 : "=r"(r[0]), "=r"(r[1]), "=r"(r[2]), "=r"(r[3]) : "r"(addr));
}
__device__ __forceinline__ void mma16816(float* d, const uint32_t* a,
                                         uint32_t b0, uint32_t b1) {
    asm volatile("mma.sync.aligned.m16n8k16.row.col.f32.f16.f16.f32 "
                 "{%0,%1,%2,%3}, {%4,%5,%6,%7}, {%8,%9}, {%0,%1,%2,%3};"
                 : "+f"(d[0]), "+f"(d[1]), "+f"(d[2]), "+f"(d[3])
                 : "r"(a[0]), "r"(a[1]), "r"(a[2]), "r"(a[3]), "r"(b0), "r"(b1));
}
__device__ __forceinline__ void cpa16(uint32_t dst, const void* src, uint32_t sz) {
    asm volatile("cp.async.cg.shared.global [%0], [%1], 16, %2;"
                 :: "r"(dst), "l"(src), "r"(sz) : "memory");
}
#define CP_COMMIT() asm volatile("cp.async.commit_group;" ::: "memory")
#define CP_WAIT(n)  asm volatile("cp.async.wait_group %0;" :: "n"(n) : "memory")

// ---------------- fused conversion + router kernel ----------------
#define XN    ((size_t)TT * HH / 4)
#define W2N   ((size_t)NE * 2 * IMOE * HH / 4)
#define DWN   ((size_t)NE * HH * IMOE / 4)
#define SW2N  ((size_t)2 * ISH * HH / 4)
#define SDWN  ((size_t)HH * ISH / 4)
#define CVT_TOTAL (XN + W2N + DWN + SW2N + SDWN)   // 22,675,456 (divisible by 1024)
#define CVT_ITERS 4
#define CVT_NBLK  ((unsigned)((CVT_TOTAL + 256 * CVT_ITERS - 1) / (256 * CVT_ITERS)))
#define ROUTER_NBLK (TT / 8)   // 256 blocks, 8 tokens each (one warp per token)

__device__ __forceinline__ void cvt_map(size_t i,
    const float4* x, const float4* gw, const float4* uw, const float4* dw,
    const float4* sgw, const float4* suw, const float4* sdw,
    __half2* x16, __half2* w2, __half2* dw16, __half2* sw2, __half2* sdw16,
    const float4*& s, __half2*& d) {
    if (i < XN) { s = x + i; d = x16 + 2 * i; return; }
    i -= XN;
    if (i < W2N) {
        const int K4 = HH / 4;
        int    k4  = (int)(i % K4);
        size_t row = i / K4;
        int    n   = (int)(row % (2 * IMOE));
        int    e   = (int)(row / (2 * IMOE));
        s = ((n & 1) ? uw : gw) + ((size_t)e * IMOE + (n >> 1)) * K4 + k4;
        d = w2 + 2 * i;
        return;
    }
    i -= W2N;
    if (i < DWN) { s = dw + i; d = dw16 + 2 * i; return; }
    i -= DWN;
    if (i < SW2N) {
        const int K4 = HH / 4;
        int    k4  = (int)(i % K4);
        size_t row = i / K4;
        int    n   = (int)(row % (2 * ISH));
        s = ((n & 1) ? suw : sgw) + (size_t)(n >> 1) * K4 + k4;
        d = sw2 + 2 * i;
        return;
    }
    i -= SW2N;
    s = sdw + i; d = sdw16 + 2 * i;
}

__global__ void cvt_router(const float4* __restrict__ x4,
                           const float4* __restrict__ gw, const float4* __restrict__ uw,
                           const float4* __restrict__ dw,
                           const float4* __restrict__ sgw, const float4* __restrict__ suw,
                           const float4* __restrict__ sdw,
                           __half2* __restrict__ x16, __half2* __restrict__ w2,
                           __half2* __restrict__ dw16, __half2* __restrict__ sw2,
                           __half2* __restrict__ sdw16,
                           const float* __restrict__ x,
                           const float* __restrict__ rw,
                           const float* __restrict__ bias) {
    if (blockIdx.x < CVT_NBLK) {
        // ---- conversion path: 4 indices per thread, loads batched for MLP ----
        size_t base = (size_t)blockIdx.x * (256 * CVT_ITERS) + threadIdx.x;
        const float4* s[CVT_ITERS];
        __half2*      d[CVT_ITERS];
        float4        v[CVT_ITERS];
#pragma unroll
        for (int it = 0; it < CVT_ITERS; it++) {
            size_t i = base + (size_t)it * 256;
            if (i < CVT_TOTAL) {
                cvt_map(i, x4, gw, uw, dw, sgw, suw, sdw,
                        x16, w2, dw16, sw2, sdw16, s[it], d[it]);
            } else {
                s[it] = nullptr;
            }
        }
#pragma unroll
        for (int it = 0; it < CVT_ITERS; it++)
            if (s[it]) v[it] = *s[it];
#pragma unroll
        for (int it = 0; it < CVT_ITERS; it++) {
            if (s[it]) {
                d[it][0] = __half2(__float2half_rn(v[it].x), __float2half_rn(v[it].y));
                d[it][1] = __half2(__float2half_rn(v[it].z), __float2half_rn(v[it].w));
            }
        }
        return;
    }

    // ---- router path (bit-identical to previous router_kernel) ----
    int t    = ((int)(blockIdx.x - CVT_NBLK) * blockDim.x + threadIdx.x) >> 5;
    int lane = threadIdx.x & 31;
    if (t >= TT) return;
    const float* xt = x + (size_t)t * HH;

    float logits[NE];
#pragma unroll
    for (int e = 0; e < NE; e++) {
        const float* w = rw + e * HH;
        float sum = 0.f;
        for (int h = lane; h < HH; h += 32) sum = fmaf(xt[h], w[h], sum);
#pragma unroll
        for (int o = 16; o; o >>= 1) sum += __shfl_xor_sync(0xffffffffu, sum, o);
        logits[e] = sum;
    }
    if (lane != 0) return;

    float scores[NE], sfc[NE];
#pragma unroll
    for (int e = 0; e < NE; e++) {
        scores[e] = 1.f / (1.f + expf(-logits[e]));
        sfc[e]    = scores[e] + bias[e];
    }
    float gs[4];
#pragma unroll
    for (int g = 0; g < 4; g++) gs[g] = sfc[2 * g] + sfc[2 * g + 1];
    int g0 = 0;
#pragma unroll
    for (int g = 1; g < 4; g++) if (gs[g] > gs[g0]) g0 = g;
    int g1 = -1;
#pragma unroll
    for (int g = 0; g < 4; g++) {
        if (g == g0) continue;
        if (g1 < 0 || gs[g] > gs[g1]) g1 = g;
    }
    int i0 = -1; float v0 = -1.f;
#pragma unroll
    for (int e = 0; e < NE; e++) {
        int g = e >> 1;
        float v = (g == g0 || g == g1) ? sfc[e] : 0.0f;
        if (v > v0) { v0 = v; i0 = e; }
    }
    int i1 = -1; float v1 = -1.f;
#pragma unroll
    for (int e = 0; e < NE; e++) {
        if (e == i0) continue;
        int g = e >> 1;
        float v = (g == g0 || g == g1) ? sfc[e] : 0.0f;
        if (v > v1) { v1 = v; i1 = e; }
    }
    float w0 = scores[i0], w1 = scores[i1];
    float inv = 2.5f / (w0 + w1 + 1e-20f);
    w0 *= inv; w1 *= inv;

    int p0 = atomicAdd(&g_cnt[i0], 1);
    g_rows[i0 * TT + p0] = t;
    g_tok2row[t * 2 + 0] = i0 * TT + p0;
    g_wt[t * 2 + 0]      = w0;
    int p1 = atomicAdd(&g_cnt[i1], 1);
    g_rows[i1 * TT + p1] = t;
    g_tok2row[t * 2 + 1] = i1 * TT + p1;
    g_wt[t * 2 + 1]      = w1;
}

// ---------------- misc ----------------
__global__ void zero_cnt_kernel() {
    if (threadIdx.x < NE) g_cnt[threadIdx.x] = 0;
}

// ---------------- fp16 HMMA GEMM: D[M,N] = A[M,K] @ B[N,K]^T ----------------
// 128x64 CTA tile, BK=32, 8 warps (4m x 2n), warp tile 32x32,
// 3-stage cp.async pipeline, single __syncthreads per chunk, 3 CTAs/SM.
// COMBINE variant (final shared-down GEMM): epilogue adds routed contributions.
#define ROWB   80
#define APLANE (128 * ROWB)       // 10240
#define BPLANE (64 * ROWB)        // 5120
#define STAGEB (APLANE + BPLANE)  // 15360
#define NSTG   3
#define SMEM_SZ (NSTG * STAGEB)   // 46080

template <int N, int K, bool ROUTED, bool GATHER, bool GATEUP, bool COMBINE>
__global__ __launch_bounds__(256, 3)
void hmma1(const __half* __restrict__ A, const __half* __restrict__ B,
           float* __restrict__ D, __half* __restrict__ P,
           const float* __restrict__ YR) {
    extern __shared__ __align__(128) char smem[];
    const int e  = blockIdx.z;
    const int M  = ROUTED ? g_cnt[e] : TT;
    const int m0 = blockIdx.y * 128;
    if (m0 >= M) return;
    const int n0   = blockIdx.x * 64;
    const int tid  = threadIdx.x;
    const int lane = tid & 31;
    const int wid  = tid >> 5;
    const int wm   = wid & 3;      // 4 m-slices of 32
    const int wn   = wid >> 2;     // 2 n-slices of 32
    const uint32_t sb0 = smem_u32(smem);

    // A loader: 2 threads per row (all 256 threads), 32B each
    const int lr = tid >> 1;
    const int hh = tid & 1;
    const __half* pA;
    uint32_t asz = 0;
    {
        int row = m0 + lr;
        size_t gr = 0;
        if (row < M) {
            gr  = GATHER ? (size_t)g_rows[e * TT + row]
                         : (ROUTED ? (size_t)e * TT + row : (size_t)row);
            asz = 16;
        }
        pA = A + gr * (size_t)K + hh * 16;
    }
    // B loader: threads <128, 2 threads per row (64 rows), 32B each
    const bool ldB = tid < 128;
    const __half* pB = B + (ROUTED ? (size_t)e * N * K : 0)
                         + (size_t)(n0 + (lr & 63)) * K + hh * 16;
    const uint32_t dstA = (uint32_t)lr * ROWB + (uint32_t)hh * 32;
    const uint32_t dstB = APLANE + (uint32_t)(lr & 63) * ROWB + (uint32_t)hh * 32;

    auto issue = [&](int c, int s) {
        uint32_t d = sb0 + (uint32_t)s * STAGEB;
        const __half* a0 = pA + c * 32;
        cpa16(d + dstA,      a0,     asz);
        cpa16(d + dstA + 16, a0 + 8, asz);
        if (ldB) {
            const __half* b0 = pB + c * 32;
            cpa16(d + dstB,      b0,     16);
            cpa16(d + dstB + 16, b0 + 8, 16);
        }
        CP_COMMIT();
    };

    float acc[2][4][4];
#pragma unroll
    for (int f = 0; f < 2; f++)
#pragma unroll
        for (int j = 0; j < 4; j++)
#pragma unroll
            for (int q = 0; q < 4; q++) acc[f][j][q] = 0.f;

    // hoisted ldsm row offsets (stage-invariant)
    const uint32_t raBase0 = (uint32_t)(wm * 32 + (lane & 15)) * ROWB;
    const uint32_t raBase1 = (uint32_t)(wm * 32 + 16 + (lane & 15)) * ROWB;
    const uint32_t rbBase0 = APLANE + (uint32_t)(wn * 32 + (lane & 15)) * ROWB;
    const uint32_t rbBase1 = APLANE + (uint32_t)(wn * 32 + 16 + (lane & 15)) * ROWB;
    const uint32_t cbHalf  = (uint32_t)((lane >> 4) * 8) * 2;

    const int NCH = K / 32;
    issue(0, 0);
    issue(1, 1);

    int s = 0;          // stage of chunk c (manual wrap, no %)
    int sNext = 2;      // stage of chunk c+2
    for (int c = 0; c < NCH; c++) {
        if (c + 1 < NCH) {
            CP_WAIT(1);
        } else {
            CP_WAIT(0);
        }
        __syncthreads();
        if (c + 2 < NCH) issue(c + 2, sNext);

        const uint32_t stg = sb0 + (uint32_t)s * STAGEB;
#pragma unroll
        for (int ks = 0; ks < 2; ks++) {
            const uint32_t cb = cbHalf + (uint32_t)(ks * 32);
            uint32_t aF[2][4], bF[4][2];
            ldsm4(aF[0], stg + raBase0 + cb);
            ldsm4(aF[1], stg + raBase1 + cb);
            {
                uint32_t h4[4];
                ldsm4(h4, stg + rbBase0 + cb);
                bF[0][0] = h4[0]; bF[0][1] = h4[2];
                bF[1][0] = h4[1]; bF[1][1] = h4[3];
                ldsm4(h4, stg + rbBase1 + cb);
                bF[2][0] = h4[0]; bF[2][1] = h4[2];
                bF[3][0] = h4[1]; bF[3][1] = h4[3];
            }
#pragma unroll
            for (int f = 0; f < 2; f++)
#pragma unroll
                for (int j = 0; j < 4; j++)
                    mma16816(acc[f][j], aF[f], bF[j][0], bF[j][1]);
        }
        s     = (s     == NSTG - 1) ? 0 : s + 1;
        sNext = (sNext == NSTG - 1) ? 0 : sNext + 1;
    }

    // ---- epilogue ----
    const size_t rowbase = ROUTED ? (size_t)e * TT : 0;
#pragma unroll
    for (int f = 0; f < 2; f++) {
#pragma unroll
        for (int half = 0; half < 2; half++) {
            int rloc = m0 + wm * 32 + f * 16 + (lane >> 2) + half * 8;
            if (rloc >= M) continue;
            size_t rg = rowbase + rloc;
            size_t r0 = 0, r1 = 0;
            float  cw0 = 0.f, cw1 = 0.f;
            if (COMBINE) {
                r0  = (size_t)g_tok2row[2 * rloc];
                r1  = (size_t)g_tok2row[2 * rloc + 1];
                cw0 = g_wt[2 * rloc];
                cw1 = g_wt[2 * rloc + 1];
            }
#pragma unroll
            for (int j = 0; j < 4; j++) {
                float vx = acc[f][j][half * 2 + 0];
                float vy = acc[f][j][half * 2 + 1];
                int cg = n0 + wn * 32 + j * 8 + (lane & 3) * 2;
                if (GATEUP) {
                    // vx = gate (even col), vy = up (odd col)
                    float a = vx / (1.f + expf(-vx)) * vy;
                    P[rg * (size_t)(N / 2) + (cg >> 1)] = __float2half_rn(a);
                } else if (COMBINE) {
                    float2 a = *(const float2*)(YR + r0 * (size_t)N + cg);
                    float2 b = *(const float2*)(YR + r1 * (size_t)N + cg);
                    float ox = fmaf(cw0, a.x, fmaf(cw1, b.x, vx));
                    float oy = fmaf(cw0, a.y, fmaf(cw1, b.y, vy));
                    *(float2*)(D + rg * (size_t)N + cg) = make_float2(ox, oy);
                } else {
                    *(float2*)(D + rg * (size_t)N + cg) = make_float2(vx, vy);
                }
            }
        }
    }
}

// ---------------- launch ----------------
extern "C" void kernel_launch(void* const* d_in, const int* in_sizes, int n_in,
                              void* d_out, int out_size) {
    const float* x    = (const float*)d_in[0];
    const float* rw   = (const float*)d_in[1];
    const float* bias = (const float*)d_in[2];
    const float* gw   = (const float*)d_in[3];
    const float* uw   = (const float*)d_in[4];
    const float* dw   = (const float*)d_in[5];
    const float* sgw  = (const float*)d_in[6];
    const float* suw  = (const float*)d_in[7];
    const float* sdw  = (const float*)d_in[8];
    float* out = (float*)d_out;

    __half *x16, *w2, *dwp, *sw2, *sdwp, *act, *acs;
    float *py;
    cudaGetSymbolAddress((void**)&x16,  g_x16);
    cudaGetSymbolAddress((void**)&w2,   g_w2);
    cudaGetSymbolAddress((void**)&dwp,  g_dw);
    cudaGetSymbolAddress((void**)&sw2,  g_sw2);
    cudaGetSymbolAddress((void**)&sdwp, g_sdw);
    cudaGetSymbolAddress((void**)&act,  g_act);
    cudaGetSymbolAddress((void**)&acs,  g_acs);
    cudaGetSymbolAddress((void**)&py,   g_y);

    cudaFuncSetAttribute(hmma1<2 * IMOE, HH, true,  true,  true,  false>, cudaFuncAttributeMaxDynamicSharedMemorySize, SMEM_SZ);
    cudaFuncSetAttribute(hmma1<HH, IMOE, true,  false, false, false>, cudaFuncAttributeMaxDynamicSharedMemorySize, SMEM_SZ);
    cudaFuncSetAttribute(hmma1<2 * ISH,  HH, false, false, true,  false>, cudaFuncAttributeMaxDynamicSharedMemorySize, SMEM_SZ);
    cudaFuncSetAttribute(hmma1<HH,  ISH, false, false, false, true >, cudaFuncAttributeMaxDynamicSharedMemorySize, SMEM_SZ);

    // node order (2 hidden harness launches precede these):
    zero_cnt_kernel<<<1, 32>>>();                                     // 0
    // 1: conversions + router in one launch (router blocks appended)
    cvt_router<<<CVT_NBLK + ROUTER_NBLK, 256>>>(
        (const float4*)x, (const float4*)gw, (const float4*)uw, (const float4*)dw,
        (const float4*)sgw, (const float4*)suw, (const float4*)sdw,
        (__half2*)x16, (__half2*)w2, (__half2*)dwp, (__half2*)sw2, (__half2*)sdwp,
        x, rw, bias);

    // 2: MAIN routed gate+up GEMM
    hmma1<2 * IMOE, HH, true, true, true, false><<<dim3(2 * IMOE / 64, TT / 128, NE), 256, SMEM_SZ>>>(
        x16, w2, nullptr, act, nullptr);
    // 3: routed down GEMM -> g_y
    hmma1<HH, IMOE, true, false, false, false><<<dim3(HH / 64, TT / 128, NE), 256, SMEM_SZ>>>(
        act, dwp, py, nullptr, nullptr);
    // 4: shared gate+up GEMM
    hmma1<2 * ISH, HH, false, false, true, false><<<dim3(2 * ISH / 64, TT / 128, 1), 256, SMEM_SZ>>>(
        x16, sw2, nullptr, acs, nullptr);
    // 5: shared down GEMM with fused combine -> out
    hmma1<HH, ISH, false, false, false, true><<<dim3(HH / 64, TT / 128, 1), 256, SMEM_SZ>>>(
        acs, sdwp, out, nullptr, py);
}